// round 5
// baseline (speedup 1.0000x reference)
#include <cuda_runtime.h>
#include <cstdint>

constexpr int M = 1024;
constexpr int N = 32768;
constexpr int K = 512;
constexpr float MARGIN = 0.3f;

constexpr float QSCALE  = 31.75f;               // int8 quant scale (4 sigma -> 127)
constexpr float INV_QS2 = 1.0f / (QSCALE * QSCALE);

constexpr int BM = 128, BN = 256, BK = 32;
constexpr int NCH = K / BK;                     // 16
constexpr int NSTAGE = 3;

// dynamic smem layout (int8 tiles, 32B rows, no padding needed)
constexpr uint32_t OFF_LAB = 0;                         // 256 ints = 1KB
constexpr uint32_t OFF_A   = 1024;
constexpr uint32_t A_STAGE = BM * BK;                   // 4096
constexpr uint32_t OFF_B   = OFF_A + NSTAGE * A_STAGE;  // 13312
constexpr uint32_t B_STAGE = BN * BK;                   // 8192
constexpr uint32_t SMEM_TOTAL = OFF_B + NSTAGE * B_STAGE;  // 37888 (<48KB: no attr)

__device__ float g_pos[M];
__device__ float g_neg[M];
__device__ int8_t g_Aq[M * K];
__device__ int8_t g_Bq[(size_t)N * K];

__device__ __forceinline__ float f_inf()  { return __int_as_float(0x7f800000); }
__device__ __forceinline__ float f_ninf() { return __int_as_float(0xff800000); }

__device__ __forceinline__ void atomicMinF(float* a, float v) {
    if (v >= 0.f) atomicMin((int*)a, __float_as_int(v));
    else          atomicMax((unsigned int*)a, __float_as_uint(v));
}
__device__ __forceinline__ void atomicMaxF(float* a, float v) {
    if (v >= 0.f) atomicMax((int*)a, __float_as_int(v));
    else          atomicMin((unsigned int*)a, __float_as_uint(v));
}

__device__ __forceinline__ uint32_t smem_u32(const void* p) {
    uint32_t a;
    asm("{ .reg .u64 t; cvta.to.shared.u64 t, %1; cvt.u32.u64 %0, t; }" : "=r"(a) : "l"(p));
    return a;
}
__device__ __forceinline__ uint32_t lds32(uint32_t addr) {
    uint32_t v;
    asm volatile("ld.shared.u32 %0, [%1];" : "=r"(v) : "r"(addr));
    return v;
}
__device__ __forceinline__ void mma_s8(int* d, const uint32_t* a, const uint32_t* b) {
    asm volatile(
        "mma.sync.aligned.m16n8k32.row.col.s32.s8.s8.s32 "
        "{%0,%1,%2,%3}, {%4,%5,%6,%7}, {%8,%9}, {%0,%1,%2,%3};"
        : "+r"(d[0]), "+r"(d[1]), "+r"(d[2]), "+r"(d[3])
        : "r"(a[0]), "r"(a[1]), "r"(a[2]), "r"(a[3]), "r"(b[0]), "r"(b[1]));
}
__device__ __forceinline__ void cp_async16(uint32_t dst, const void* src) {
    asm volatile("cp.async.cg.shared.global [%0], [%1], 16;" :: "r"(dst), "l"(src));
}
__device__ __forceinline__ void cp_commit() {
    asm volatile("cp.async.commit_group;" ::: "memory");
}
template <int NG> __device__ __forceinline__ void cp_wait() {
    asm volatile("cp.async.wait_group %0;" :: "n"(NG) : "memory");
}

__device__ __forceinline__ uint32_t quant4(float4 v) {
    int q0 = __float2int_rn(fminf(fmaxf(v.x, -4.f), 4.f) * QSCALE);
    int q1 = __float2int_rn(fminf(fmaxf(v.y, -4.f), 4.f) * QSCALE);
    int q2 = __float2int_rn(fminf(fmaxf(v.z, -4.f), 4.f) * QSCALE);
    int q3 = __float2int_rn(fminf(fmaxf(v.w, -4.f), 4.f) * QSCALE);
    return (uint32_t)(q0 & 0xff) | ((uint32_t)(q1 & 0xff) << 8) |
           ((uint32_t)(q2 & 0xff) << 16) | ((uint32_t)(q3 & 0xff) << 24);
}

// Quantize fp32 -> int8 scratch; also init per-row min/max arrays.
__global__ void tl_quant(const float* __restrict__ A, const float* __restrict__ B) {
    const int gid = blockIdx.x * blockDim.x + threadIdx.x;
    const int nth = gridDim.x * blockDim.x;
    if (gid < M) { g_pos[gid] = f_inf(); g_neg[gid] = f_ninf(); }
    for (int i = gid; i < M * K / 4; i += nth)
        *reinterpret_cast<uint32_t*>(g_Aq + (size_t)i * 4) =
            quant4(*reinterpret_cast<const float4*>(A + (size_t)i * 4));
    for (size_t i = gid; i < (size_t)N * K / 4; i += nth)
        *reinterpret_cast<uint32_t*>(g_Bq + i * 4) =
            quant4(*reinterpret_cast<const float4*>(B + i * 4));
}

__global__ __launch_bounds__(512)
void tl_gemm(const int* __restrict__ targets, const int* __restrict__ idxv,
             const int* __restrict__ labels)
{
    extern __shared__ __align__(128) char smem[];
    __shared__ int   sT[BM];
    __shared__ int   sI[BM];
    __shared__ float sPos[BM];
    __shared__ float sNeg[BM];

    const uint32_t sb = smem_u32(smem);
    const uint32_t sA = sb + OFF_A;
    const uint32_t sB = sb + OFF_B;
    int* sLab = (int*)(smem + OFF_LAB);

    const int tid  = threadIdx.x;
    const int lane = tid & 31;
    const int wid  = tid >> 5;
    const int rowBase = blockIdx.y * BM;
    const int colBase = blockIdx.x * BN;

    // 16 warps: 4 (m) x 4 (n); warp tile 32 x 64
    const int warp_m = (wid >> 2) * 32;
    const int warp_n = (wid & 3) * 64;

    for (int i = tid; i < BN; i += 512) sLab[i] = labels[colBase + i];
    if (tid < BM) {
        sT[tid] = targets[rowBase + tid];
        sI[tid] = idxv[rowBase + tid];
        sPos[tid] = f_inf(); sNeg[tid] = f_ninf();
    }

    // stage loader: A = 256 x 16B chunks (tid<256), B = 512 x 16B (one/thread)
    auto load_stage = [&](int st, int c) {
        const int kb = c * BK;
        if (tid < 256) {
            const int r = tid >> 1, q = tid & 1;
            cp_async16(sA + st * A_STAGE + r * BK + q * 16,
                       g_Aq + (size_t)(rowBase + r) * K + kb + q * 16);
        }
        {
            const int r = tid >> 1, q = tid & 1;
            cp_async16(sB + st * B_STAGE + r * BK + q * 16,
                       g_Bq + (size_t)(colBase + r) * K + kb + q * 16);
        }
        cp_commit();
    };

    // fragment base offsets (m16n8k32: 4 consecutive k-bytes per register)
    const uint32_t lr4 = (lane >> 2);          // row/col within 8-group
    const uint32_t lk4 = (lane & 3) * 4;       // k byte offset
    const uint32_t aBase = (uint32_t)(warp_m + lr4) * BK + lk4;
    const uint32_t bBase = (uint32_t)(warp_n + lr4) * BK + lk4;

    int acc[2][8][4] = {};

    load_stage(0, 0);
    load_stage(1, 1);

#pragma unroll 1
    for (int c = 0; c < NCH; ++c) {
        if (c + 1 < NCH) cp_wait<1>(); else cp_wait<0>();
        __syncthreads();
        if (c + 2 < NCH) load_stage((c + 2) % NSTAGE, c + 2);

        const uint32_t stA = sA + (c % NSTAGE) * A_STAGE;
        const uint32_t stB = sB + (c % NSTAGE) * B_STAGE;

        uint32_t af[2][4], bf[8][2];
#pragma unroll
        for (int mi = 0; mi < 2; ++mi) {
            const uint32_t a0 = stA + aBase + mi * 16 * BK;
            af[mi][0] = lds32(a0);
            af[mi][1] = lds32(a0 + 8 * BK);
            af[mi][2] = lds32(a0 + 16);
            af[mi][3] = lds32(a0 + 8 * BK + 16);
        }
#pragma unroll
        for (int ni = 0; ni < 8; ++ni) {
            const uint32_t b0 = stB + bBase + ni * 8 * BK;
            bf[ni][0] = lds32(b0);
            bf[ni][1] = lds32(b0 + 16);
        }
#pragma unroll
        for (int mi = 0; mi < 2; ++mi)
#pragma unroll
            for (int ni = 0; ni < 8; ++ni)
                mma_s8(acc[mi][ni], af[mi], bf[ni]);
    }
    __syncthreads();

    // Epilogue: scale to fp32 similarity, masked min/max.
    const int lq = lane >> 2;
    const int lr = (lane & 3) * 2;
#pragma unroll
    for (int mi = 0; mi < 2; ++mi) {
#pragma unroll
        for (int h = 0; h < 2; ++h) {
            const int rloc = warp_m + mi * 16 + h * 8 + lq;
            const int tg = sT[rloc];
            const int ix = sI[rloc];
            float pmin = f_inf(), nmax = f_ninf();
#pragma unroll
            for (int ni = 0; ni < 8; ++ni) {
#pragma unroll
                for (int j = 0; j < 2; ++j) {
                    const int cloc = warp_n + ni * 8 + lr + j;
                    const float v = (float)acc[mi][ni][h * 2 + j] * INV_QS2;
                    if (sLab[cloc] == tg) {
                        if (colBase + cloc != ix) pmin = fminf(pmin, v);
                    } else {
                        nmax = fmaxf(nmax, v);
                    }
                }
            }
            atomicMinF(&sPos[rloc], pmin);
            atomicMaxF(&sNeg[rloc], nmax);
        }
    }
    __syncthreads();

    if (tid < BM) {
        const float p = sPos[tid], q = sNeg[tid];
        if (p <  f_inf())  atomicMinF(&g_pos[rowBase + tid], p);
        if (q > f_ninf())  atomicMaxF(&g_neg[rowBase + tid], q);
    }
}

__global__ void tl_final(float* __restrict__ out) {
    __shared__ float red[32];
    const int i = threadIdx.x;
    float l = fmaxf(g_neg[i] - g_pos[i] + MARGIN, 0.0f);
#pragma unroll
    for (int o = 16; o > 0; o >>= 1) l += __shfl_xor_sync(0xffffffffu, l, o);
    if ((i & 31) == 0) red[i >> 5] = l;
    __syncthreads();
    if (i < 32) {
        float s = red[i];
#pragma unroll
        for (int o = 16; o > 0; o >>= 1) s += __shfl_xor_sync(0xffffffffu, s, o);
        if (i == 0) out[0] = s * (1.0f / (float)M);
    }
}

extern "C" void kernel_launch(void* const* d_in, const int* in_sizes, int n_in,
                              void* d_out, int out_size) {
    const float* A       = (const float*)d_in[0];
    const float* B       = (const float*)d_in[1];
    const int*   targets = (const int*)  d_in[2];
    const int*   idxv    = (const int*)  d_in[3];
    const int*   labels  = (const int*)  d_in[4];
    float*       out     = (float*)d_out;

    tl_quant<<<1024, 256>>>(A, B);
    dim3 grid(N / BN, M / BM);   // 128 x 8 = 1024 CTAs
    tl_gemm<<<grid, 512, SMEM_TOTAL>>>(targets, idxv, labels);
    tl_final<<<1, M>>>(out);
}

// round 6
// speedup vs baseline: 1.9526x; 1.9526x over previous
#include <cuda_runtime.h>
#include <cuda_fp8.h>
#include <cstdint>

constexpr int M = 1024;
constexpr int N = 32768;
constexpr int K = 512;
constexpr float MARGIN = 0.3f;

constexpr int BM = 128, BN = 256, BK = 32;
constexpr int NCH = K / BK;                     // 16
constexpr int NSTAGE = 3;
constexpr int ROWB = 48;                        // 32B data + 16B pad (conflict-free LDSM)

// dynamic smem layout
constexpr uint32_t OFF_LAB = 0;                         // 256 ints = 1KB
constexpr uint32_t OFF_A   = 1024;
constexpr uint32_t A_STAGE = BM * ROWB;                 // 6144
constexpr uint32_t OFF_B   = OFF_A + NSTAGE * A_STAGE;  // 19456
constexpr uint32_t B_STAGE = BN * ROWB;                 // 12288
constexpr uint32_t SMEM_TOTAL = OFF_B + NSTAGE * B_STAGE;  // 56320

__device__ float g_pos[M];
__device__ float g_neg[M];
__device__ uint8_t g_Aq[M * K];
__device__ uint8_t g_Bq[(size_t)N * K];

__device__ __forceinline__ float f_inf()  { return __int_as_float(0x7f800000); }
__device__ __forceinline__ float f_ninf() { return __int_as_float(0xff800000); }

__device__ __forceinline__ void atomicMinF(float* a, float v) {
    if (v >= 0.f) atomicMin((int*)a, __float_as_int(v));
    else          atomicMax((unsigned int*)a, __float_as_uint(v));
}
__device__ __forceinline__ void atomicMaxF(float* a, float v) {
    if (v >= 0.f) atomicMax((int*)a, __float_as_int(v));
    else          atomicMin((unsigned int*)a, __float_as_uint(v));
}

__device__ __forceinline__ uint32_t smem_u32(const void* p) {
    uint32_t a;
    asm("{ .reg .u64 t; cvta.to.shared.u64 t, %1; cvt.u32.u64 %0, t; }" : "=r"(a) : "l"(p));
    return a;
}
__device__ __forceinline__ void ldsm_x4(uint32_t* r, uint32_t addr) {
    asm volatile("ldmatrix.sync.aligned.m8n8.x4.shared.b16 {%0,%1,%2,%3}, [%4];"
                 : "=r"(r[0]), "=r"(r[1]), "=r"(r[2]), "=r"(r[3]) : "r"(addr));
}
__device__ __forceinline__ void mma_e4m3(float* d, const uint32_t* a, const uint32_t* b) {
    asm volatile(
        "mma.sync.aligned.m16n8k32.row.col.f32.e4m3.e4m3.f32 "
        "{%0,%1,%2,%3}, {%4,%5,%6,%7}, {%8,%9}, {%0,%1,%2,%3};"
        : "+f"(d[0]), "+f"(d[1]), "+f"(d[2]), "+f"(d[3])
        : "r"(a[0]), "r"(a[1]), "r"(a[2]), "r"(a[3]), "r"(b[0]), "r"(b[1]));
}
__device__ __forceinline__ void cp_async16(uint32_t dst, const void* src) {
    asm volatile("cp.async.cg.shared.global [%0], [%1], 16;" :: "r"(dst), "l"(src));
}
__device__ __forceinline__ void cp_commit() {
    asm volatile("cp.async.commit_group;" ::: "memory");
}
template <int NG> __device__ __forceinline__ void cp_wait() {
    asm volatile("cp.async.wait_group %0;" :: "n"(NG) : "memory");
}

__device__ __forceinline__ uint32_t fp8quad(float4 v) {
    __nv_fp8x2_storage_t lo =
        __nv_cvt_float2_to_fp8x2(make_float2(v.x, v.y), __NV_SATFINITE, __NV_E4M3);
    __nv_fp8x2_storage_t hi =
        __nv_cvt_float2_to_fp8x2(make_float2(v.z, v.w), __NV_SATFINITE, __NV_E4M3);
    return (uint32_t)lo | ((uint32_t)hi << 16);
}

// Convert fp32 -> e4m3 scratch; init per-row min/max arrays.
__global__ void tl_quant(const float* __restrict__ A, const float* __restrict__ B) {
    const int gid = blockIdx.x * blockDim.x + threadIdx.x;
    const int nth = gridDim.x * blockDim.x;
    if (gid < M) { g_pos[gid] = f_inf(); g_neg[gid] = f_ninf(); }
    for (int i = gid; i < M * K / 4; i += nth)
        *reinterpret_cast<uint32_t*>(g_Aq + (size_t)i * 4) =
            fp8quad(*reinterpret_cast<const float4*>(A + (size_t)i * 4));
    for (size_t i = gid; i < (size_t)N * K / 4; i += nth)
        *reinterpret_cast<uint32_t*>(g_Bq + i * 4) =
            fp8quad(*reinterpret_cast<const float4*>(B + i * 4));
}

__global__ __launch_bounds__(512)
void tl_gemm(const int* __restrict__ targets, const int* __restrict__ idxv,
             const int* __restrict__ labels)
{
    extern __shared__ __align__(128) char smem[];
    __shared__ int   sT[BM];
    __shared__ int   sI[BM];
    __shared__ float sPos[BM];
    __shared__ float sNeg[BM];

    const uint32_t sb = smem_u32(smem);
    const uint32_t sA = sb + OFF_A;
    const uint32_t sB = sb + OFF_B;
    int* sLab = (int*)(smem + OFF_LAB);

    const int tid  = threadIdx.x;
    const int lane = tid & 31;
    const int wid  = tid >> 5;
    const int rowBase = blockIdx.y * BM;
    const int colBase = blockIdx.x * BN;

    // 16 warps: 4 (m) x 4 (n); warp tile 32 x 64
    const int warp_m = (wid >> 2) * 32;
    const int warp_n = (wid & 3) * 64;

    for (int i = tid; i < BN; i += 512) sLab[i] = labels[colBase + i];
    if (tid < BM) {
        sT[tid] = targets[rowBase + tid];
        sI[tid] = idxv[rowBase + tid];
        sPos[tid] = f_inf(); sNeg[tid] = f_ninf();
    }

    // stage loader: A rows 128 x 2 chunks (tid<256), B rows 256 x 2 chunks (one/thread)
    auto load_stage = [&](int st, int c) {
        const int kb = c * BK;
        if (tid < 256) {
            const int r = tid >> 1, q = tid & 1;
            cp_async16(sA + st * A_STAGE + r * ROWB + q * 16,
                       g_Aq + (size_t)(rowBase + r) * K + kb + q * 16);
        }
        {
            const int r = tid >> 1, q = tid & 1;
            cp_async16(sB + st * B_STAGE + r * ROWB + q * 16,
                       g_Bq + (size_t)(colBase + r) * K + kb + q * 16);
        }
        cp_commit();
    };

    // ldmatrix source addresses (within a stage)
    // A (x4): matrices = [rows 0-7, b0-15], [rows 8-15, b0-15], [rows 0-7, b16-31], [rows 8-15, b16-31]
    const uint32_t aOff = (uint32_t)(warp_m + (lane & 15)) * ROWB + (lane >> 4) * 16;
    // B (x4): [cols 0-7, h0], [cols 0-7, h1], [cols 8-15, h0], [cols 8-15, h1]
    const uint32_t bOff = (uint32_t)(warp_n + (lane & 7) + ((lane >> 4) & 1) * 8) * ROWB
                        + ((lane >> 3) & 1) * 16;

    float acc[2][8][4] = {};

    load_stage(0, 0);
    load_stage(1, 1);

#pragma unroll 1
    for (int c = 0; c < NCH; ++c) {
        if (c + 1 < NCH) cp_wait<1>(); else cp_wait<0>();
        __syncthreads();
        if (c + 2 < NCH) load_stage((c + 2) % NSTAGE, c + 2);

        const uint32_t stA = sA + (c % NSTAGE) * A_STAGE;
        const uint32_t stB = sB + (c % NSTAGE) * B_STAGE;

        uint32_t af[2][4], bf[4][4];
#pragma unroll
        for (int mi = 0; mi < 2; ++mi)
            ldsm_x4(af[mi], stA + aOff + mi * 16 * ROWB);
#pragma unroll
        for (int p = 0; p < 4; ++p)
            ldsm_x4(bf[p], stB + bOff + p * 16 * ROWB);

#pragma unroll
        for (int mi = 0; mi < 2; ++mi)
#pragma unroll
            for (int ni = 0; ni < 8; ++ni)
                mma_e4m3(acc[mi][ni], af[mi], &bf[ni >> 1][(ni & 1) * 2]);
    }
    __syncthreads();

    // Epilogue: masked min/max (sims are raw fp32 accumulators).
    const int lq = lane >> 2;
    const int lr = (lane & 3) * 2;
#pragma unroll
    for (int mi = 0; mi < 2; ++mi) {
#pragma unroll
        for (int h = 0; h < 2; ++h) {
            const int rloc = warp_m + mi * 16 + h * 8 + lq;
            const int tg = sT[rloc];
            const int ix = sI[rloc];
            float pmin = f_inf(), nmax = f_ninf();
#pragma unroll
            for (int ni = 0; ni < 8; ++ni) {
#pragma unroll
                for (int j = 0; j < 2; ++j) {
                    const int cloc = warp_n + ni * 8 + lr + j;
                    const float v = acc[mi][ni][h * 2 + j];
                    if (sLab[cloc] == tg) {
                        if (colBase + cloc != ix) pmin = fminf(pmin, v);
                    } else {
                        nmax = fmaxf(nmax, v);
                    }
                }
            }
            atomicMinF(&sPos[rloc], pmin);
            atomicMaxF(&sNeg[rloc], nmax);
        }
    }
    __syncthreads();

    if (tid < BM) {
        const float p = sPos[tid], q = sNeg[tid];
        if (p <  f_inf())  atomicMinF(&g_pos[rowBase + tid], p);
        if (q > f_ninf())  atomicMaxF(&g_neg[rowBase + tid], q);
    }
}

__global__ void tl_final(float* __restrict__ out) {
    __shared__ float red[32];
    const int i = threadIdx.x;
    float l = fmaxf(g_neg[i] - g_pos[i] + MARGIN, 0.0f);
#pragma unroll
    for (int o = 16; o > 0; o >>= 1) l += __shfl_xor_sync(0xffffffffu, l, o);
    if ((i & 31) == 0) red[i >> 5] = l;
    __syncthreads();
    if (i < 32) {
        float s = red[i];
#pragma unroll
        for (int o = 16; o > 0; o >>= 1) s += __shfl_xor_sync(0xffffffffu, s, o);
        if (i == 0) out[0] = s * (1.0f / (float)M);
    }
}

extern "C" void kernel_launch(void* const* d_in, const int* in_sizes, int n_in,
                              void* d_out, int out_size) {
    const float* A       = (const float*)d_in[0];
    const float* B       = (const float*)d_in[1];
    const int*   targets = (const int*)  d_in[2];
    const int*   idxv    = (const int*)  d_in[3];
    const int*   labels  = (const int*)  d_in[4];
    float*       out     = (float*)d_out;

    static bool attrSet = false;
    if (!attrSet) {
        cudaFuncSetAttribute(tl_gemm, cudaFuncAttributeMaxDynamicSharedMemorySize,
                             SMEM_TOTAL);
        attrSet = true;
    }

    tl_quant<<<1024, 256>>>(A, B);
    dim3 grid(N / BN, M / BM);   // 128 x 8 = 1024 CTAs
    tl_gemm<<<grid, 512, SMEM_TOTAL>>>(targets, idxv, labels);
    tl_final<<<1, M>>>(out);
}